// round 13
// baseline (speedup 1.0000x reference)
#include <cuda_runtime.h>
#include <cuda_bf16.h>
#include <mma.h>

using namespace nvcuda;

#define B_ 64
#define S_ 512
#define I_ 256
#define O_ 256
#define KP 800   // stacked K': [hi | lo | hi | bias,0...] -> B' [Whi | Whi | Wlo | bias]

typedef unsigned long long ULL;

// Scratch: xg[m][n], m = s*64 + b (32768), n = gate*256 + o (1024). 134 MB.
__device__ float g_xg[(size_t)S_ * B_ * 4 * O_];
// bf16 split weights (B' only; A' converts in-GEMM)
__device__ __nv_bfloat16 g_bbf[(size_t)1024 * KP];    // 1.6 MB

// ---------------------------------------------------------------------------
// helpers
// ---------------------------------------------------------------------------
__device__ __forceinline__ ULL ffma2(ULL a, ULL b, ULL c) {
    ULL d;
    asm("fma.rn.f32x2 %0, %1, %2, %3;" : "=l"(d) : "l"(a), "l"(b), "l"(c));
    return d;
}
__device__ __forceinline__ float f2lo(ULL v) { return __uint_as_float((unsigned)v); }
__device__ __forceinline__ float f2hi(ULL v) { return __uint_as_float((unsigned)(v >> 32)); }
__device__ __forceinline__ float sigf(float x) { return 1.0f / (1.0f + __expf(-x)); }
__device__ __forceinline__ float tanhx(float x) { return 2.0f * sigf(2.0f * x) - 1.0f; }
__device__ __forceinline__ unsigned smem_u32(const void* p) {
    return (unsigned)__cvta_generic_to_shared(p);
}
__device__ __forceinline__ unsigned mapa_rank(unsigned local_addr, int rank) {
    unsigned ra;
    asm volatile("mapa.shared::cluster.u32 %0, %1, %2;"
                 : "=r"(ra) : "r"(local_addr), "r"(rank));
    return ra;
}
__device__ __forceinline__ void mbar_init(unsigned mbar, unsigned cnt) {
    asm volatile("mbarrier.init.shared.b64 [%0], %1;" :: "r"(mbar), "r"(cnt) : "memory");
}
__device__ __forceinline__ void mbar_arm_tx(unsigned mbar, unsigned tx) {
    asm volatile("mbarrier.arrive.expect_tx.shared.b64 _, [%0], %1;"
                 :: "r"(mbar), "r"(tx) : "memory");
}
__device__ __forceinline__ void mbar_wait_cluster(unsigned mbar, unsigned parity) {
    asm volatile(
        "{\n\t.reg .pred P1;\n\t"
        "WAIT_%=:\n\t"
        "mbarrier.try_wait.parity.acquire.cluster.shared::cta.b64 P1, [%0], %1, 0x989680;\n\t"
        "@P1 bra.uni DONE_%=;\n\t"
        "bra.uni WAIT_%=;\n\t"
        "DONE_%=:\n\t}"
        :: "r"(mbar), "r"(parity) : "memory");
}
__device__ __forceinline__ void dsm_bulk_copy(unsigned dst_cluster, unsigned src_cta,
                                              unsigned bytes, unsigned mbar_cluster) {
    asm volatile(
        "cp.async.bulk.shared::cluster.shared::cta.mbarrier::complete_tx::bytes "
        "[%0], [%1], %2, [%3];"
        :: "r"(dst_cluster), "r"(src_cta), "r"(bytes), "r"(mbar_cluster) : "memory");
}

// ---------------------------------------------------------------------------
// B' conversion: [Whi | Whi | Wlo | bias_hi, bias_lo, 0...]
// ---------------------------------------------------------------------------
__global__ void conv_w_kernel(const float* __restrict__ Wx,
                              const float* __restrict__ bx,
                              const float* __restrict__ bh) {
    const int n = blockIdx.x;          // 0..1023
    const int t = threadIdx.x;
    const float f = Wx[(size_t)n * I_ + t];
    const __nv_bfloat16 hi = __float2bfloat16(f);
    const __nv_bfloat16 lo = __float2bfloat16(f - __bfloat162float(hi));
    __nv_bfloat16* row = g_bbf + (size_t)n * KP;
    row[t]       = hi;
    row[256 + t] = hi;
    row[512 + t] = lo;
    if (t < 32) {
        __nv_bfloat16 v = __float2bfloat16(0.0f);
        if (t < 2) {
            const float bias = bx[n] + bh[n];
            const __nv_bfloat16 bhi = __float2bfloat16(bias);
            v = (t == 0) ? bhi : __float2bfloat16(bias - __bfloat162float(bhi));
        }
        row[768 + t] = v;
    }
}

// ---------------------------------------------------------------------------
// Phase 1: xg = A'(32768 x 800) @ B'^T via wmma bf16; A' converted on the fly
//   from x. BM=BN=128, BK=32, 256 thr, 8 warps (4m x 2n), warp tile 32x64.
// ---------------------------------------------------------------------------
#define BKG 32
#define KSTAGES (KP / BKG)   // 25

__global__ void __launch_bounds__(256, 1) gemm_bf16_kernel(
    const float* __restrict__ x) {
    __shared__ __align__(16) __nv_bfloat16 As[2][128][BKG + 8];
    __shared__ __align__(16) __nv_bfloat16 Bs[2][128][BKG + 8];

    const int t  = threadIdx.x;
    const int bn = blockIdx.x;   // 0..7
    const int bm = blockIdx.y;   // 0..255
    const int wid = t >> 5;
    const int wm = wid & 3;
    const int wn = wid >> 2;

    const int row  = t >> 1;     // 0..127
    const int half = t & 1;
    const int m = bm * 128 + row;
    const float* xrow = x + ((size_t)(m & 63) * S_ + (m >> 6)) * I_ + half * 16;
    const __nv_bfloat16* bg = g_bbf + (size_t)(bn * 128 + row) * KP + half * 16;

    wmma::fragment<wmma::accumulator, 16, 16, 16, float> cf[2][4];
#pragma unroll
    for (int i = 0; i < 2; ++i)
#pragma unroll
        for (int j = 0; j < 4; ++j) wmma::fill_fragment(cf[i][j], 0.0f);

    // A-stage converter: stage ks -> 16 bf16 in av[]
    float4 xf[4];
    uint4 pb0, pb1;
    // prefetch stage 0
#pragma unroll
    for (int q = 0; q < 4; ++q) xf[q] = *(const float4*)(xrow + q * 4);
    pb0 = *(const uint4*)(bg);
    pb1 = *(const uint4*)(bg + 8);

    for (int ks = 0; ks < KSTAGES; ++ks) {
        const int cur = ks & 1;
        // convert A chunk for this stage
        __nv_bfloat16 av[16];
        if (ks < 24) {
            const int seg = ks >> 3;
#pragma unroll
            for (int q = 0; q < 4; ++q) {
                const float* fp = (const float*)&xf[q];
#pragma unroll
                for (int j = 0; j < 4; ++j) {
                    const float f = fp[j];
                    const __nv_bfloat16 hi = __float2bfloat16(f);
                    av[q * 4 + j] = (seg == 1)
                        ? __float2bfloat16(f - __bfloat162float(hi)) : hi;
                }
            }
        } else {
#pragma unroll
            for (int j = 0; j < 16; ++j)
                av[j] = __float2bfloat16(
                    (half == 0 && j < 2) ? 1.0f : 0.0f);
        }
        *(uint4*)&As[cur][row][half * 16]     = *(uint4*)&av[0];
        *(uint4*)&As[cur][row][half * 16 + 8] = *(uint4*)&av[8];
        *(uint4*)&Bs[cur][row][half * 16]     = pb0;
        *(uint4*)&Bs[cur][row][half * 16 + 8] = pb1;
        __syncthreads();
        if (ks + 1 < KSTAGES) {
            if (ks + 1 < 24) {
                const int ks2 = ks + 1;
                const float* xp = xrow + ((ks2 & 7) * 32);
#pragma unroll
                for (int q = 0; q < 4; ++q) xf[q] = *(const float4*)(xp + q * 4);
            }
            pb0 = *(const uint4*)(bg + (ks + 1) * BKG);
            pb1 = *(const uint4*)(bg + (ks + 1) * BKG + 8);
        }
#pragma unroll
        for (int k16 = 0; k16 < 2; ++k16) {
            wmma::fragment<wmma::matrix_a, 16, 16, 16, __nv_bfloat16,
                           wmma::row_major> af[2];
            wmma::fragment<wmma::matrix_b, 16, 16, 16, __nv_bfloat16,
                           wmma::col_major> bfr[4];
#pragma unroll
            for (int i = 0; i < 2; ++i)
                wmma::load_matrix_sync(af[i],
                    &As[cur][wm * 32 + i * 16][k16 * 16], BKG + 8);
#pragma unroll
            for (int j = 0; j < 4; ++j)
                wmma::load_matrix_sync(bfr[j],
                    &Bs[cur][wn * 64 + j * 16][k16 * 16], BKG + 8);
#pragma unroll
            for (int i = 0; i < 2; ++i)
#pragma unroll
                for (int j = 0; j < 4; ++j)
                    wmma::mma_sync(cf[i][j], af[i], bfr[j], cf[i][j]);
        }
    }

#pragma unroll
    for (int i = 0; i < 2; ++i) {
        const int mm = bm * 128 + wm * 32 + i * 16;
#pragma unroll
        for (int j = 0; j < 4; ++j) {
            const int n = bn * 128 + wn * 64 + j * 16;
            wmma::store_matrix_sync(g_xg + (size_t)mm * 1024 + n, cf[i][j],
                                    1024, wmma::mem_row_major);
        }
    }
}

// ---------------------------------------------------------------------------
// Phase 2: 32 clusters x 4 CTAs, 2 batches/cluster, rank r owns 256 gate-rows.
//   Reg chunks (blocks r, r+1): thread = 1 row x 2 batches (wpr 128 regs).
//   Smem chunks (blocks r+2, r+3): thread = rows {t>>1, (t>>1)+128} x batch
//   (t&1) -> one h LDS.128 per k4 serves both batches (wf halved).
//   Partials merge via gsmA (reg half) + gsmB (smem half).
//   Handoff: per-warp 128B bulk copies issued right after each cell warp's
//   writes (early issue), per-source mbars, rotated consumption.
// ---------------------------------------------------------------------------
// dynamic smem (bytes):
//   [0, 131072)        ulonglong2 wS[2][16][256]  ([j][k4][row])
//   [131072, 135168)   float h[2][512]            (parity x 4 blocks x 128 f)
//   [135168, 137344)   float gsmA[2][272]
//   [137344, 139520)   float gsmB[2][272]
//   [139520, 139584)   ULL mbar[8]                (m = src*2 + parity)
#define SM_WS    0
#define SM_HS    131072
#define SM_GA    135168
#define SM_GB    137344
#define SM_MBAR  139520
#define SM_TOTAL 139584
#define GS       272

__global__ void __cluster_dims__(4, 1, 1) __launch_bounds__(256, 1)
lstm_rec_kernel(const float* __restrict__ h0, const float* __restrict__ c0,
                const float* __restrict__ Wh, float* __restrict__ out) {
    extern __shared__ __align__(16) unsigned char smraw[];
    ulonglong2* wS = (ulonglong2*)(smraw + SM_WS);
    float* h_sf    = (float*)(smraw + SM_HS);
    float* gsmA    = (float*)(smraw + SM_GA);
    float* gsmB    = (float*)(smraw + SM_GB);

    const int t   = threadIdx.x;
    const int r   = blockIdx.x & 3;
    const int cid = blockIdx.x >> 2;
    const int pr  = t >> 1;           // row-pair id (smem half)
    const int bb  = t & 1;            // batch (smem half)

    const int grow = (t >> 6) * 256 + r * 64 + (t & 63);
    const float* wrow = Wh + (size_t)grow * 256;

    // register weights: blocks {r, (r+1)&3} for gate-row t
    ULL wpr[2][32];
#pragma unroll
    for (int j = 0; j < 2; ++j) {
        const int blk = (r + j) & 3;
#pragma unroll
        for (int k2 = 0; k2 < 32; ++k2)
            wpr[j][k2] = *(const ULL*)(wrow + blk * 64 + 2 * k2);
    }

    // smem weights: blocks {(r+2)&3, (r+3)&3}, layout [j][k4][row]
    for (int idx = t; idx < 2 * 16 * 256; idx += 256) {
        const int j = idx >> 12, k4 = (idx >> 8) & 15, rw = idx & 255;
        const int grw = (rw >> 6) * 256 + r * 64 + (rw & 63);
        const int blk = (r + 2 + j) & 3;
        float4 v = *(const float4*)(Wh + (size_t)grw * 256 + blk * 64 + k4 * 4);
        wS[(j * 16 + k4) * 256 + rw] = *(ulonglong2*)&v;
    }

    const unsigned mb_base = smem_u32(smraw + SM_MBAR);
    if (t == 0) {
#pragma unroll
        for (int m = 0; m < 8; ++m) mbar_init(mb_base + m * 8, 1u);
    }
    __syncthreads();
    if (t == 0) {
#pragma unroll
        for (int src = 0; src < 4; ++src) {
            if (src == r) continue;
            mbar_arm_tx(mb_base + (src * 2 + 0) * 8, 512u);
            mbar_arm_tx(mb_base + (src * 2 + 1) * 8, 512u);
        }
    }

    // h0 into parity-0 buffer (blocked layout)
    {
        const int k = t;
        const int rk = k >> 6, kl = k & 63;
        const int base = rk * 128 + (kl >> 2) * 8 + (kl & 3);
#pragma unroll
        for (int b = 0; b < 2; ++b)
            h_sf[base + b * 4] = h0[(size_t)(cid * 2 + b) * 256 + k];
    }
    __syncthreads();
    asm volatile("barrier.cluster.arrive.aligned;" ::: "memory");
    asm volatile("barrier.cluster.wait.aligned;" ::: "memory");

    const bool cell = (t < 128);
    const int o_c = t >> 1, b_c = t & 1;
    const int o_g = r * 64 + o_c;
    const int b_g = cid * 2 + b_c;
    float creg = cell ? c0[(size_t)b_g * 256 + o_g] : 0.0f;

    float xgv[4];
    if (cell) {
        const float* xp = g_xg + (size_t)(0 * 64 + b_g) * 1024 + o_g;
#pragma unroll
        for (int gg = 0; gg < 4; ++gg) xgv[gg] = __ldcg(xp + gg * 256);
    }

    float* hT = out + (size_t)B_ * S_ * O_;
    float* cT = hT + (size_t)B_ * O_;
    const unsigned hs_base = smem_u32(h_sf);
    unsigned parmask = 0u;

    int p = 0;
    for (int s = 0; s < S_; ++s, p ^= 1) {
        const float* hp = h_sf + p * 512;
        ULL acc0 = 0ULL, acc1 = 0ULL;   // reg half: row t, batches 0/1
        ULL sA = 0ULL, sB = 0ULL;       // smem half: rows pr / pr+128, batch bb

        // chunk 0: own block (registers, no wait)
        {
            const float* hb = hp + r * 128;
#pragma unroll
            for (int k4 = 0; k4 < 16; ++k4) {
                const ulonglong2 h0v = *(const ulonglong2*)(hb + k4 * 8);
                const ulonglong2 h1v = *(const ulonglong2*)(hb + k4 * 8 + 4);
                acc0 = ffma2(h0v.x, wpr[0][2 * k4], acc0);
                acc0 = ffma2(h0v.y, wpr[0][2 * k4 + 1], acc0);
                acc1 = ffma2(h1v.x, wpr[0][2 * k4], acc1);
                acc1 = ffma2(h1v.y, wpr[0][2 * k4 + 1], acc1);
            }
        }
        // chunk 1: block (r+1)&3 (registers)
        {
            const int blk = (r + 1) & 3;
            if (s > 0) {
                const int m = blk * 2 + p;
                mbar_wait_cluster(mb_base + m * 8u, (parmask >> m) & 1u);
                parmask ^= (1u << m);
            }
            const float* hb = hp + blk * 128;
#pragma unroll
            for (int k4 = 0; k4 < 16; ++k4) {
                const ulonglong2 h0v = *(const ulonglong2*)(hb + k4 * 8);
                const ulonglong2 h1v = *(const ulonglong2*)(hb + k4 * 8 + 4);
                acc0 = ffma2(h0v.x, wpr[1][2 * k4], acc0);
                acc0 = ffma2(h0v.y, wpr[1][2 * k4 + 1], acc0);
                acc1 = ffma2(h1v.x, wpr[1][2 * k4], acc1);
                acc1 = ffma2(h1v.y, wpr[1][2 * k4 + 1], acc1);
            }
        }
        // chunks 2,3: smem weights, lane-parity batch split
#pragma unroll
        for (int j = 0; j < 2; ++j) {
            const int blk = (r + 2 + j) & 3;
            if (s > 0) {
                const int m = blk * 2 + p;
                mbar_wait_cluster(mb_base + m * 8u, (parmask >> m) & 1u);
                parmask ^= (1u << m);
            }
            const float* hb = hp + blk * 128 + bb * 4;
            const ulonglong2* wbA = wS + (size_t)(j * 16) * 256 + pr;
#pragma unroll
            for (int k4 = 0; k4 < 16; ++k4) {
                const ulonglong2 hv = *(const ulonglong2*)(hb + k4 * 8);
                const ulonglong2 wA = wbA[k4 * 256];
                const ulonglong2 wB = wbA[k4 * 256 + 128];
                sA = ffma2(hv.x, wA.x, sA);
                sA = ffma2(hv.y, wA.y, sA);
                sB = ffma2(hv.x, wB.x, sB);
                sB = ffma2(hv.y, wB.y, sB);
            }
        }

        if (s > 0 && t < 3) {
            const int src = (r + 1 + t) & 3;
            mbar_arm_tx(mb_base + (unsigned)(src * 2 + p) * 8u, 512u);
        }

        gsmA[t]      = f2lo(acc0) + f2hi(acc0);
        gsmA[GS + t] = f2lo(acc1) + f2hi(acc1);
        gsmB[bb * GS + pr]       = f2lo(sA) + f2hi(sA);
        gsmB[bb * GS + pr + 128] = f2lo(sB) + f2hi(sB);
        __syncthreads();

        if (cell) {
            const float* gA = gsmA + b_c * GS;
            const float* gB = gsmB + b_c * GS;
            const float gf = gA[o_c]       + gB[o_c]       + xgv[0];
            const float gi = gA[64 + o_c]  + gB[64 + o_c]  + xgv[1];
            const float gc = gA[128 + o_c] + gB[128 + o_c] + xgv[2];
            const float go = gA[192 + o_c] + gB[192 + o_c] + xgv[3];
            const float fg  = sigf(gf);
            const float ig  = sigf(gi);
            const float cg  = tanhx(gc);
            const float ogt = sigf(go);
            creg = creg * fg + ig * cg;
            const float hv = ogt * tanhx(creg);
            out[((size_t)b_g * S_ + s) * 256 + o_g] = hv;
            if (s == S_ - 1) {
                hT[(size_t)b_g * 256 + o_g] = hv;
                cT[(size_t)b_g * 256 + o_g] = creg;
            } else {
                const int q = p ^ 1;
                const int boff = (o_c >> 2) * 8 + b_c * 4 + (o_c & 3);
                h_sf[q * 512 + r * 128 + boff] = hv;   // own block (copy src)
                // early per-warp publication: warp w's slice = 128B at w*32
                __syncwarp();
                const int lw = t & 31;
                if (lw < 3) {
                    asm volatile("fence.proxy.async.shared::cta;" ::: "memory");
                    const int w4 = t >> 5;            // 0..3
                    const int dr = (r + 1 + lw) & 3;
                    const unsigned src = hs_base +
                        (unsigned)(q * 512 + r * 128 + w4 * 32) * 4u;
                    const unsigned dst = mapa_rank(src, dr);
                    const unsigned mbr = mapa_rank(
                        mb_base + (unsigned)(r * 2 + q) * 8u, dr);
                    dsm_bulk_copy(dst, src, 128u, mbr);
                }
            }
        }
        __syncthreads();

        if (s < S_ - 1 && cell) {
            const float* xp = g_xg + (size_t)((s + 1) * 64 + b_g) * 1024 + o_g;
#pragma unroll
            for (int gg = 0; gg < 4; ++gg) xgv[gg] = __ldcg(xp + gg * 256);
        }
    }

    asm volatile("barrier.cluster.arrive.aligned;" ::: "memory");
    asm volatile("barrier.cluster.wait.aligned;" ::: "memory");
}

// ---------------------------------------------------------------------------
// launch
// ---------------------------------------------------------------------------
extern "C" void kernel_launch(void* const* d_in, const int* in_sizes, int n_in,
                              void* d_out, int out_size) {
    (void)in_sizes; (void)n_in; (void)out_size;
    const float* x  = (const float*)d_in[0];
    const float* h0 = (const float*)d_in[1];
    const float* c0 = (const float*)d_in[2];
    const float* Wh = (const float*)d_in[3];
    const float* bh = (const float*)d_in[4];
    const float* Wx = (const float*)d_in[5];
    const float* bx = (const float*)d_in[6];
    float* out = (float*)d_out;

    cudaFuncSetAttribute(lstm_rec_kernel,
                         cudaFuncAttributeMaxDynamicSharedMemorySize, SM_TOTAL);

    conv_w_kernel<<<1024, 256>>>(Wx, bx, bh);
    gemm_bf16_kernel<<<dim3(8, 256), 256>>>(x);
    lstm_rec_kernel<<<128, 256, SM_TOTAL>>>(h0, c0, Wh, out);
}

// round 14
// speedup vs baseline: 1.0433x; 1.0433x over previous
#include <cuda_runtime.h>
#include <cuda_bf16.h>
#include <mma.h>

using namespace nvcuda;

#define B_ 64
#define S_ 512
#define I_ 256
#define O_ 256
#define KP 800   // stacked K': [hi | lo | hi | bias,0...] -> B' [Whi | Whi | Wlo | bias]

typedef unsigned long long ULL;

// Scratch: xg[m][n], m = s*64 + b (32768), n = gate*256 + o (1024). 134 MB.
__device__ float g_xg[(size_t)S_ * B_ * 4 * O_];
// bf16 split operands
__device__ __nv_bfloat16 g_abf[(size_t)32768 * KP];   // 52.4 MB
__device__ __nv_bfloat16 g_bbf[(size_t)1024 * KP];    // 1.6 MB

// ---------------------------------------------------------------------------
// helpers
// ---------------------------------------------------------------------------
__device__ __forceinline__ ULL ffma2(ULL a, ULL b, ULL c) {
    ULL d;
    asm("fma.rn.f32x2 %0, %1, %2, %3;" : "=l"(d) : "l"(a), "l"(b), "l"(c));
    return d;
}
__device__ __forceinline__ float f2lo(ULL v) { return __uint_as_float((unsigned)v); }
__device__ __forceinline__ float f2hi(ULL v) { return __uint_as_float((unsigned)(v >> 32)); }
__device__ __forceinline__ float sigf(float x) { return 1.0f / (1.0f + __expf(-x)); }
__device__ __forceinline__ float tanhx(float x) { return 2.0f * sigf(2.0f * x) - 1.0f; }
__device__ __forceinline__ unsigned smem_u32(const void* p) {
    return (unsigned)__cvta_generic_to_shared(p);
}
__device__ __forceinline__ unsigned mapa_rank(unsigned local_addr, int rank) {
    unsigned ra;
    asm volatile("mapa.shared::cluster.u32 %0, %1, %2;"
                 : "=r"(ra) : "r"(local_addr), "r"(rank));
    return ra;
}
__device__ __forceinline__ void mbar_init(unsigned mbar, unsigned cnt) {
    asm volatile("mbarrier.init.shared.b64 [%0], %1;" :: "r"(mbar), "r"(cnt) : "memory");
}
__device__ __forceinline__ void mbar_arm_tx(unsigned mbar, unsigned tx) {
    asm volatile("mbarrier.arrive.expect_tx.shared.b64 _, [%0], %1;"
                 :: "r"(mbar), "r"(tx) : "memory");
}
__device__ __forceinline__ void mbar_wait_cluster(unsigned mbar, unsigned parity) {
    asm volatile(
        "{\n\t.reg .pred P1;\n\t"
        "WAIT_%=:\n\t"
        "mbarrier.try_wait.parity.acquire.cluster.shared::cta.b64 P1, [%0], %1, 0x989680;\n\t"
        "@P1 bra.uni DONE_%=;\n\t"
        "bra.uni WAIT_%=;\n\t"
        "DONE_%=:\n\t}"
        :: "r"(mbar), "r"(parity) : "memory");
}
__device__ __forceinline__ void dsm_bulk_copy(unsigned dst_cluster, unsigned src_cta,
                                              unsigned bytes, unsigned mbar_cluster) {
    asm volatile(
        "cp.async.bulk.shared::cluster.shared::cta.mbarrier::complete_tx::bytes "
        "[%0], [%1], %2, [%3];"
        :: "r"(dst_cluster), "r"(src_cta), "r"(bytes), "r"(mbar_cluster) : "memory");
}

// ---------------------------------------------------------------------------
// Phase 1a: bf16-split conversion (as R12).
// ---------------------------------------------------------------------------
__global__ void conv_x_kernel(const float* __restrict__ x) {
    const int m = blockIdx.x;          // 0..32767
    const int t = threadIdx.x;         // 0..255
    const int b = m & 63, s = m >> 6;
    const float f = x[((size_t)b * S_ + s) * I_ + t];
    const __nv_bfloat16 hi = __float2bfloat16(f);
    const __nv_bfloat16 lo = __float2bfloat16(f - __bfloat162float(hi));
    __nv_bfloat16* row = g_abf + (size_t)m * KP;
    row[t]       = hi;
    row[256 + t] = lo;
    row[512 + t] = hi;
    if (t < 32)
        row[768 + t] = __float2bfloat16((t < 2) ? 1.0f : 0.0f);
}

__global__ void conv_w_kernel(const float* __restrict__ Wx,
                              const float* __restrict__ bx,
                              const float* __restrict__ bh) {
    const int n = blockIdx.x;          // 0..1023
    const int t = threadIdx.x;
    const float f = Wx[(size_t)n * I_ + t];
    const __nv_bfloat16 hi = __float2bfloat16(f);
    const __nv_bfloat16 lo = __float2bfloat16(f - __bfloat162float(hi));
    __nv_bfloat16* row = g_bbf + (size_t)n * KP;
    row[t]       = hi;
    row[256 + t] = hi;
    row[512 + t] = lo;
    if (t < 32) {
        __nv_bfloat16 v = __float2bfloat16(0.0f);
        if (t < 2) {
            const float bias = bx[n] + bh[n];
            const __nv_bfloat16 bhi = __float2bfloat16(bias);
            v = (t == 0) ? bhi : __float2bfloat16(bias - __bfloat162float(bhi));
        }
        row[768 + t] = v;
    }
}

// ---------------------------------------------------------------------------
// Phase 1b: xg = A' (32768 x 800) @ B'^T (800 x 1024) via wmma bf16 (as R12).
// ---------------------------------------------------------------------------
#define BKG 32
#define KSTAGES (KP / BKG)   // 25

__global__ void __launch_bounds__(256, 1) gemm_bf16_kernel() {
    __shared__ __align__(16) __nv_bfloat16 As[2][128][BKG + 8];
    __shared__ __align__(16) __nv_bfloat16 Bs[2][128][BKG + 8];

    const int t  = threadIdx.x;
    const int bn = blockIdx.x;   // 0..7
    const int bm = blockIdx.y;   // 0..255
    const int wid = t >> 5;
    const int wm = wid & 3;
    const int wn = wid >> 2;

    const int row  = t >> 1;     // 0..127
    const int half = t & 1;
    const __nv_bfloat16* ag = g_abf + (size_t)(bm * 128 + row) * KP + half * 16;
    const __nv_bfloat16* bg = g_bbf + (size_t)(bn * 128 + row) * KP + half * 16;

    wmma::fragment<wmma::accumulator, 16, 16, 16, float> cf[2][4];
#pragma unroll
    for (int i = 0; i < 2; ++i)
#pragma unroll
        for (int j = 0; j < 4; ++j) wmma::fill_fragment(cf[i][j], 0.0f);

    uint4 pa0 = *(const uint4*)(ag);
    uint4 pa1 = *(const uint4*)(ag + 8);
    uint4 pb0 = *(const uint4*)(bg);
    uint4 pb1 = *(const uint4*)(bg + 8);

    for (int ks = 0; ks < KSTAGES; ++ks) {
        const int cur = ks & 1;
        *(uint4*)&As[cur][row][half * 16]     = pa0;
        *(uint4*)&As[cur][row][half * 16 + 8] = pa1;
        *(uint4*)&Bs[cur][row][half * 16]     = pb0;
        *(uint4*)&Bs[cur][row][half * 16 + 8] = pb1;
        __syncthreads();
        if (ks + 1 < KSTAGES) {
            pa0 = *(const uint4*)(ag + (ks + 1) * BKG);
            pa1 = *(const uint4*)(ag + (ks + 1) * BKG + 8);
            pb0 = *(const uint4*)(bg + (ks + 1) * BKG);
            pb1 = *(const uint4*)(bg + (ks + 1) * BKG + 8);
        }
#pragma unroll
        for (int k16 = 0; k16 < 2; ++k16) {
            wmma::fragment<wmma::matrix_a, 16, 16, 16, __nv_bfloat16,
                           wmma::row_major> af[2];
            wmma::fragment<wmma::matrix_b, 16, 16, 16, __nv_bfloat16,
                           wmma::col_major> bfr[4];
#pragma unroll
            for (int i = 0; i < 2; ++i)
                wmma::load_matrix_sync(af[i],
                    &As[cur][wm * 32 + i * 16][k16 * 16], BKG + 8);
#pragma unroll
            for (int j = 0; j < 4; ++j)
                wmma::load_matrix_sync(bfr[j],
                    &Bs[cur][wn * 64 + j * 16][k16 * 16], BKG + 8);
#pragma unroll
            for (int i = 0; i < 2; ++i)
#pragma unroll
                for (int j = 0; j < 4; ++j)
                    wmma::mma_sync(cf[i][j], af[i], bfr[j], cf[i][j]);
        }
    }

#pragma unroll
    for (int i = 0; i < 2; ++i) {
        const int m = bm * 128 + wm * 32 + i * 16;
#pragma unroll
        for (int j = 0; j < 4; ++j) {
            const int n = bn * 128 + wn * 64 + j * 16;
            wmma::store_matrix_sync(g_xg + (size_t)m * 1024 + n, cf[i][j],
                                    1024, wmma::mem_row_major);
        }
    }
}

// ---------------------------------------------------------------------------
// Phase 2: R12 structure; ONLY change = lane-parity batch split on smem
//   chunks (2/3): thread = rows {t>>1, (t>>1)+128} x batch (t&1); one 16B
//   h load per k4 serves both parities (1 wf vs 2). Partials in gsmB.
//   Copy protocol, arm placement, everything else identical to R12.
// ---------------------------------------------------------------------------
// dynamic smem (bytes):
//   [0, 131072)        ulonglong2 wS[2][16][256]  ([j][k4][row])
//   [131072, 135168)   float h[2][512]            (parity x 4 blocks x 128 f)
//   [135168, 137344)   float gsmA[2][272]
//   [137344, 139520)   float gsmB[2][272]
//   [139520, 139584)   ULL mbar[8]                (m = src*2 + parity)
#define SM_WS    0
#define SM_HS    131072
#define SM_GA    135168
#define SM_GB    137344
#define SM_MBAR  139520
#define SM_TOTAL 139584
#define GS       272

__global__ void __cluster_dims__(4, 1, 1) __launch_bounds__(256, 1)
lstm_rec_kernel(const float* __restrict__ h0, const float* __restrict__ c0,
                const float* __restrict__ Wh, float* __restrict__ out) {
    extern __shared__ __align__(16) unsigned char smraw[];
    ulonglong2* wS = (ulonglong2*)(smraw + SM_WS);
    float* h_sf    = (float*)(smraw + SM_HS);
    float* gsmA    = (float*)(smraw + SM_GA);
    float* gsmB    = (float*)(smraw + SM_GB);

    const int t   = threadIdx.x;
    const int r   = blockIdx.x & 3;
    const int cid = blockIdx.x >> 2;
    const int pr  = t >> 1;           // row-pair id (smem half)
    const int bb  = t & 1;            // batch (smem half)

    const int grow = (t >> 6) * 256 + r * 64 + (t & 63);
    const float* wrow = Wh + (size_t)grow * 256;

    // register weights: blocks {r, (r+1)&3} for gate-row t
    ULL wpr[2][32];
#pragma unroll
    for (int j = 0; j < 2; ++j) {
        const int blk = (r + j) & 3;
#pragma unroll
        for (int k2 = 0; k2 < 32; ++k2)
            wpr[j][k2] = *(const ULL*)(wrow + blk * 64 + 2 * k2);
    }

    // smem weights: blocks {(r+2)&3, (r+3)&3}, layout [j][k4][row]
    for (int idx = t; idx < 2 * 16 * 256; idx += 256) {
        const int j = idx >> 12, k4 = (idx >> 8) & 15, rw = idx & 255;
        const int grw = (rw >> 6) * 256 + r * 64 + (rw & 63);
        const int blk = (r + 2 + j) & 3;
        float4 v = *(const float4*)(Wh + (size_t)grw * 256 + blk * 64 + k4 * 4);
        wS[(j * 16 + k4) * 256 + rw] = *(ulonglong2*)&v;
    }

    const unsigned mb_base = smem_u32(smraw + SM_MBAR);
    if (t == 0) {
#pragma unroll
        for (int m = 0; m < 8; ++m) mbar_init(mb_base + m * 8, 1u);
    }
    __syncthreads();
    if (t == 0) {
#pragma unroll
        for (int src = 0; src < 4; ++src) {
            if (src == r) continue;
            mbar_arm_tx(mb_base + (src * 2 + 0) * 8, 512u);
            mbar_arm_tx(mb_base + (src * 2 + 1) * 8, 512u);
        }
    }

    // h0 into parity-0 buffer (blocked layout)
    {
        const int k = t;
        const int rk = k >> 6, kl = k & 63;
        const int base = rk * 128 + (kl >> 2) * 8 + (kl & 3);
#pragma unroll
        for (int b = 0; b < 2; ++b)
            h_sf[base + b * 4] = h0[(size_t)(cid * 2 + b) * 256 + k];
    }
    __syncthreads();
    asm volatile("barrier.cluster.arrive.aligned;" ::: "memory");
    asm volatile("barrier.cluster.wait.aligned;" ::: "memory");

    const bool cell = (t < 128);
    const int o_c = t >> 1, b_c = t & 1;
    const int o_g = r * 64 + o_c;
    const int b_g = cid * 2 + b_c;
    float creg = cell ? c0[(size_t)b_g * 256 + o_g] : 0.0f;

    float xgv[4];
    if (cell) {
        const float* xp = g_xg + (size_t)(0 * 64 + b_g) * 1024 + o_g;
#pragma unroll
        for (int gg = 0; gg < 4; ++gg) xgv[gg] = __ldcg(xp + gg * 256);
    }

    float* hT = out + (size_t)B_ * S_ * O_;
    float* cT = hT + (size_t)B_ * O_;
    const unsigned hs_base = smem_u32(h_sf);
    unsigned parmask = 0u;

    int p = 0;
    for (int s = 0; s < S_; ++s, p ^= 1) {
        const float* hp = h_sf + p * 512;
        ULL acc0 = 0ULL, acc1 = 0ULL;   // reg half: row t, batches 0/1
        ULL sA = 0ULL, sB = 0ULL;       // smem half: rows pr / pr+128, batch bb

        // chunk 0: own block (registers, no wait)
        {
            const float* hb = hp + r * 128;
#pragma unroll
            for (int k4 = 0; k4 < 16; ++k4) {
                const ulonglong2 h0v = *(const ulonglong2*)(hb + k4 * 8);
                const ulonglong2 h1v = *(const ulonglong2*)(hb + k4 * 8 + 4);
                acc0 = ffma2(h0v.x, wpr[0][2 * k4], acc0);
                acc0 = ffma2(h0v.y, wpr[0][2 * k4 + 1], acc0);
                acc1 = ffma2(h1v.x, wpr[0][2 * k4], acc1);
                acc1 = ffma2(h1v.y, wpr[0][2 * k4 + 1], acc1);
            }
        }
        // chunk 1: block (r+1)&3 (registers)
        {
            const int blk = (r + 1) & 3;
            if (s > 0) {
                const int m = blk * 2 + p;
                mbar_wait_cluster(mb_base + m * 8u, (parmask >> m) & 1u);
                parmask ^= (1u << m);
            }
            const float* hb = hp + blk * 128;
#pragma unroll
            for (int k4 = 0; k4 < 16; ++k4) {
                const ulonglong2 h0v = *(const ulonglong2*)(hb + k4 * 8);
                const ulonglong2 h1v = *(const ulonglong2*)(hb + k4 * 8 + 4);
                acc0 = ffma2(h0v.x, wpr[1][2 * k4], acc0);
                acc0 = ffma2(h0v.y, wpr[1][2 * k4 + 1], acc0);
                acc1 = ffma2(h1v.x, wpr[1][2 * k4], acc1);
                acc1 = ffma2(h1v.y, wpr[1][2 * k4 + 1], acc1);
            }
        }
        // chunks 2,3: smem weights, lane-parity batch split
#pragma unroll
        for (int j = 0; j < 2; ++j) {
            const int blk = (r + 2 + j) & 3;
            if (s > 0) {
                const int m = blk * 2 + p;
                mbar_wait_cluster(mb_base + m * 8u, (parmask >> m) & 1u);
                parmask ^= (1u << m);
            }
            const float* hb = hp + blk * 128 + bb * 4;
            const ulonglong2* wbA = wS + (size_t)(j * 16) * 256 + pr;
#pragma unroll
            for (int k4 = 0; k4 < 16; ++k4) {
                const ulonglong2 hv = *(const ulonglong2*)(hb + k4 * 8);
                const ulonglong2 wA = wbA[k4 * 256];
                const ulonglong2 wB = wbA[k4 * 256 + 128];
                sA = ffma2(hv.x, wA.x, sA);
                sA = ffma2(hv.y, wA.y, sA);
                sB = ffma2(hv.x, wB.x, sB);
                sB = ffma2(hv.y, wB.y, sB);
            }
        }

        if (s > 0 && t < 3) {
            const int src = (r + 1 + t) & 3;
            mbar_arm_tx(mb_base + (unsigned)(src * 2 + p) * 8u, 512u);
        }

        gsmA[t]      = f2lo(acc0) + f2hi(acc0);
        gsmA[GS + t] = f2lo(acc1) + f2hi(acc1);
        gsmB[bb * GS + pr]       = f2lo(sA) + f2hi(sA);
        gsmB[bb * GS + pr + 128] = f2lo(sB) + f2hi(sB);
        __syncthreads();

        if (cell) {
            const float* gA = gsmA + b_c * GS;
            const float* gB = gsmB + b_c * GS;
            const float gf = gA[o_c]       + gB[o_c]       + xgv[0];
            const float gi = gA[64 + o_c]  + gB[64 + o_c]  + xgv[1];
            const float gc = gA[128 + o_c] + gB[128 + o_c] + xgv[2];
            const float go = gA[192 + o_c] + gB[192 + o_c] + xgv[3];
            const float fg  = sigf(gf);
            const float ig  = sigf(gi);
            const float cg  = tanhx(gc);
            const float ogt = sigf(go);
            creg = creg * fg + ig * cg;
            const float hv = ogt * tanhx(creg);
            out[((size_t)b_g * S_ + s) * 256 + o_g] = hv;
            if (s == S_ - 1) {
                hT[(size_t)b_g * 256 + o_g] = hv;
                cT[(size_t)b_g * 256 + o_g] = creg;
            } else {
                const int q = p ^ 1;
                const int boff = (o_c >> 2) * 8 + b_c * 4 + (o_c & 3);
                h_sf[q * 512 + r * 128 + boff] = hv;   // own block (copy src)
            }
        }
        __syncthreads();

        if (s < S_ - 1) {
            const int q = p ^ 1;
            if (t < 3) {
                asm volatile("fence.proxy.async.shared::cta;" ::: "memory");
                const int dr = (r + 1 + t) & 3;
                const unsigned src = hs_base + (unsigned)(q * 512 + r * 128) * 4u;
                const unsigned dst = mapa_rank(src, dr);
                const unsigned mbr = mapa_rank(mb_base + (unsigned)(r * 2 + q) * 8u, dr);
                dsm_bulk_copy(dst, src, 512u, mbr);
            }
            if (cell) {
                const float* xp = g_xg + (size_t)((s + 1) * 64 + b_g) * 1024 + o_g;
#pragma unroll
                for (int gg = 0; gg < 4; ++gg) xgv[gg] = __ldcg(xp + gg * 256);
            }
        }
    }

    asm volatile("barrier.cluster.arrive.aligned;" ::: "memory");
    asm volatile("barrier.cluster.wait.aligned;" ::: "memory");
}

// ---------------------------------------------------------------------------
// launch
// ---------------------------------------------------------------------------
extern "C" void kernel_launch(void* const* d_in, const int* in_sizes, int n_in,
                              void* d_out, int out_size) {
    (void)in_sizes; (void)n_in; (void)out_size;
    const float* x  = (const float*)d_in[0];
    const float* h0 = (const float*)d_in[1];
    const float* c0 = (const float*)d_in[2];
    const float* Wh = (const float*)d_in[3];
    const float* bh = (const float*)d_in[4];
    const float* Wx = (const float*)d_in[5];
    const float* bx = (const float*)d_in[6];
    float* out = (float*)d_out;

    cudaFuncSetAttribute(lstm_rec_kernel,
                         cudaFuncAttributeMaxDynamicSharedMemorySize, SM_TOTAL);

    conv_x_kernel<<<32768, 256>>>(x);
    conv_w_kernel<<<1024, 256>>>(Wx, bx, bh);
    gemm_bf16_kernel<<<dim3(8, 256), 256>>>();
    lstm_rec_kernel<<<128, 256, SM_TOTAL>>>(h0, c0, Wh, out);
}

// round 15
// speedup vs baseline: 1.0744x; 1.0298x over previous
#include <cuda_runtime.h>
#include <cuda_bf16.h>
#include <mma.h>

using namespace nvcuda;

#define B_ 64
#define S_ 512
#define I_ 256
#define O_ 256
#define KP 800   // stacked K': [hi | lo | hi | bias,0...] -> B' [Whi | Whi | Wlo | bias]

typedef unsigned long long ULL;

// Scratch: xg[m][n], m = s*64 + b (32768), n = gate*256 + o (1024). 134 MB.
__device__ float g_xg[(size_t)S_ * B_ * 4 * O_];
// bf16 split operands
__device__ __nv_bfloat16 g_abf[(size_t)32768 * KP];   // 52.4 MB
__device__ __nv_bfloat16 g_bbf[(size_t)1024 * KP];    // 1.6 MB

// ---------------------------------------------------------------------------
// helpers
// ---------------------------------------------------------------------------
__device__ __forceinline__ ULL ffma2(ULL a, ULL b, ULL c) {
    ULL d;
    asm("fma.rn.f32x2 %0, %1, %2, %3;" : "=l"(d) : "l"(a), "l"(b), "l"(c));
    return d;
}
__device__ __forceinline__ float f2lo(ULL v) { return __uint_as_float((unsigned)v); }
__device__ __forceinline__ float f2hi(ULL v) { return __uint_as_float((unsigned)(v >> 32)); }
__device__ __forceinline__ float sigf(float x) { return 1.0f / (1.0f + __expf(-x)); }
__device__ __forceinline__ float tanhx(float x) { return 2.0f * sigf(2.0f * x) - 1.0f; }
__device__ __forceinline__ unsigned smem_u32(const void* p) {
    return (unsigned)__cvta_generic_to_shared(p);
}
__device__ __forceinline__ unsigned mapa_rank(unsigned local_addr, int rank) {
    unsigned ra;
    asm volatile("mapa.shared::cluster.u32 %0, %1, %2;"
                 : "=r"(ra) : "r"(local_addr), "r"(rank));
    return ra;
}
__device__ __forceinline__ void mbar_init(unsigned mbar, unsigned cnt) {
    asm volatile("mbarrier.init.shared.b64 [%0], %1;" :: "r"(mbar), "r"(cnt) : "memory");
}
__device__ __forceinline__ void mbar_arm_tx(unsigned mbar, unsigned tx) {
    asm volatile("mbarrier.arrive.expect_tx.shared.b64 _, [%0], %1;"
                 :: "r"(mbar), "r"(tx) : "memory");
}
__device__ __forceinline__ void mbar_wait_cluster(unsigned mbar, unsigned parity) {
    asm volatile(
        "{\n\t.reg .pred P1;\n\t"
        "WAIT_%=:\n\t"
        "mbarrier.try_wait.parity.acquire.cluster.shared::cta.b64 P1, [%0], %1, 0x989680;\n\t"
        "@P1 bra.uni DONE_%=;\n\t"
        "bra.uni WAIT_%=;\n\t"
        "DONE_%=:\n\t}"
        :: "r"(mbar), "r"(parity) : "memory");
}
__device__ __forceinline__ void dsm_bulk_copy(unsigned dst_cluster, unsigned src_cta,
                                              unsigned bytes, unsigned mbar_cluster) {
    asm volatile(
        "cp.async.bulk.shared::cluster.shared::cta.mbarrier::complete_tx::bytes "
        "[%0], [%1], %2, [%3];"
        :: "r"(dst_cluster), "r"(src_cta), "r"(bytes), "r"(mbar_cluster) : "memory");
}

// ---------------------------------------------------------------------------
// Phase 1a: bf16-split conversion (as R12).
// ---------------------------------------------------------------------------
__global__ void conv_x_kernel(const float* __restrict__ x) {
    const int m = blockIdx.x;          // 0..32767
    const int t = threadIdx.x;         // 0..255
    const int b = m & 63, s = m >> 6;
    const float f = x[((size_t)b * S_ + s) * I_ + t];
    const __nv_bfloat16 hi = __float2bfloat16(f);
    const __nv_bfloat16 lo = __float2bfloat16(f - __bfloat162float(hi));
    __nv_bfloat16* row = g_abf + (size_t)m * KP;
    row[t]       = hi;
    row[256 + t] = lo;
    row[512 + t] = hi;
    if (t < 32)
        row[768 + t] = __float2bfloat16((t < 2) ? 1.0f : 0.0f);
}

__global__ void conv_w_kernel(const float* __restrict__ Wx,
                              const float* __restrict__ bx,
                              const float* __restrict__ bh) {
    const int n = blockIdx.x;          // 0..1023
    const int t = threadIdx.x;
    const float f = Wx[(size_t)n * I_ + t];
    const __nv_bfloat16 hi = __float2bfloat16(f);
    const __nv_bfloat16 lo = __float2bfloat16(f - __bfloat162float(hi));
    __nv_bfloat16* row = g_bbf + (size_t)n * KP;
    row[t]       = hi;
    row[256 + t] = hi;
    row[512 + t] = lo;
    if (t < 32) {
        __nv_bfloat16 v = __float2bfloat16(0.0f);
        if (t < 2) {
            const float bias = bx[n] + bh[n];
            const __nv_bfloat16 bhi = __float2bfloat16(bias);
            v = (t == 0) ? bhi : __float2bfloat16(bias - __bfloat162float(bhi));
        }
        row[768 + t] = v;
    }
}

// ---------------------------------------------------------------------------
// Phase 1b: xg = A' (32768 x 800) @ B'^T (800 x 1024) via wmma bf16 (as R12).
// ---------------------------------------------------------------------------
#define BKG 32
#define KSTAGES (KP / BKG)   // 25

__global__ void __launch_bounds__(256, 1) gemm_bf16_kernel() {
    __shared__ __align__(16) __nv_bfloat16 As[2][128][BKG + 8];
    __shared__ __align__(16) __nv_bfloat16 Bs[2][128][BKG + 8];

    const int t  = threadIdx.x;
    const int bn = blockIdx.x;   // 0..7
    const int bm = blockIdx.y;   // 0..255
    const int wid = t >> 5;
    const int wm = wid & 3;
    const int wn = wid >> 2;

    const int row  = t >> 1;     // 0..127
    const int half = t & 1;
    const __nv_bfloat16* ag = g_abf + (size_t)(bm * 128 + row) * KP + half * 16;
    const __nv_bfloat16* bg = g_bbf + (size_t)(bn * 128 + row) * KP + half * 16;

    wmma::fragment<wmma::accumulator, 16, 16, 16, float> cf[2][4];
#pragma unroll
    for (int i = 0; i < 2; ++i)
#pragma unroll
        for (int j = 0; j < 4; ++j) wmma::fill_fragment(cf[i][j], 0.0f);

    uint4 pa0 = *(const uint4*)(ag);
    uint4 pa1 = *(const uint4*)(ag + 8);
    uint4 pb0 = *(const uint4*)(bg);
    uint4 pb1 = *(const uint4*)(bg + 8);

    for (int ks = 0; ks < KSTAGES; ++ks) {
        const int cur = ks & 1;
        *(uint4*)&As[cur][row][half * 16]     = pa0;
        *(uint4*)&As[cur][row][half * 16 + 8] = pa1;
        *(uint4*)&Bs[cur][row][half * 16]     = pb0;
        *(uint4*)&Bs[cur][row][half * 16 + 8] = pb1;
        __syncthreads();
        if (ks + 1 < KSTAGES) {
            pa0 = *(const uint4*)(ag + (ks + 1) * BKG);
            pa1 = *(const uint4*)(ag + (ks + 1) * BKG + 8);
            pb0 = *(const uint4*)(bg + (ks + 1) * BKG);
            pb1 = *(const uint4*)(bg + (ks + 1) * BKG + 8);
        }
#pragma unroll
        for (int k16 = 0; k16 < 2; ++k16) {
            wmma::fragment<wmma::matrix_a, 16, 16, 16, __nv_bfloat16,
                           wmma::row_major> af[2];
            wmma::fragment<wmma::matrix_b, 16, 16, 16, __nv_bfloat16,
                           wmma::col_major> bfr[4];
#pragma unroll
            for (int i = 0; i < 2; ++i)
                wmma::load_matrix_sync(af[i],
                    &As[cur][wm * 32 + i * 16][k16 * 16], BKG + 8);
#pragma unroll
            for (int j = 0; j < 4; ++j)
                wmma::load_matrix_sync(bfr[j],
                    &Bs[cur][wn * 64 + j * 16][k16 * 16], BKG + 8);
#pragma unroll
            for (int i = 0; i < 2; ++i)
#pragma unroll
                for (int j = 0; j < 4; ++j)
                    wmma::mma_sync(cf[i][j], af[i], bfr[j], cf[i][j]);
        }
    }

#pragma unroll
    for (int i = 0; i < 2; ++i) {
        const int m = bm * 128 + wm * 32 + i * 16;
#pragma unroll
        for (int j = 0; j < 4; ++j) {
            const int n = bn * 128 + wn * 64 + j * 16;
            wmma::store_matrix_sync(g_xg + (size_t)m * 1024 + n, cf[i][j],
                                    1024, wmma::mem_row_major);
        }
    }
}

// ---------------------------------------------------------------------------
// Phase 2: exact R12 structure; ONLY change = copies issue right after a
//   cell-scoped named barrier (bar.sync 1,128) instead of after the full
//   __syncthreads — same 3x512B copies, same fence, same mbar protocol.
// ---------------------------------------------------------------------------
// dynamic smem (bytes):
//   [0, 131072)        ulonglong2 wS[2][16][256]  ([j][k4][row])
//   [131072, 135168)   float h[2][512]            (parity x 4 blocks x 128 f)
//   [135168, 137248)   float gsm[2][260]
//   [137248, 137312)   ULL mbar[8]                (m = src*2 + parity)
#define SM_WS    0
#define SM_HS    131072
#define SM_GSM   135168
#define SM_MBAR  137248
#define SM_TOTAL 137312
#define GS       260

__global__ void __cluster_dims__(4, 1, 1) __launch_bounds__(256, 1)
lstm_rec_kernel(const float* __restrict__ h0, const float* __restrict__ c0,
                const float* __restrict__ Wh, float* __restrict__ out) {
    extern __shared__ __align__(16) unsigned char smraw[];
    ulonglong2* wS = (ulonglong2*)(smraw + SM_WS);   // [j*16 + k4][row]
    float* h_sf    = (float*)(smraw + SM_HS);        // [p][512]
    float* gsm     = (float*)(smraw + SM_GSM);       // [b][GS]

    const int t   = threadIdx.x;
    const int r   = blockIdx.x & 3;        // cluster rank
    const int cid = blockIdx.x >> 2;       // 0..31

    const int grow = (t >> 6) * 256 + r * 64 + (t & 63);
    const float* wrow = Wh + (size_t)grow * 256;

    // register weights: blocks {r, (r+1)&3}
    ULL wpr[2][32];
#pragma unroll
    for (int j = 0; j < 2; ++j) {
        const int blk = (r + j) & 3;
#pragma unroll
        for (int k2 = 0; k2 < 32; ++k2)
            wpr[j][k2] = *(const ULL*)(wrow + blk * 64 + 2 * k2);
    }

    // smem weights: blocks {(r+2)&3, (r+3)&3}, layout [j][k4][row]
    for (int idx = t; idx < 2 * 16 * 256; idx += 256) {
        const int j = idx >> 12, k4 = (idx >> 8) & 15, rw = idx & 255;
        const int grw = (rw >> 6) * 256 + r * 64 + (rw & 63);
        const int blk = (r + 2 + j) & 3;
        float4 v = *(const float4*)(Wh + (size_t)grw * 256 + blk * 64 + k4 * 4);
        wS[(j * 16 + k4) * 256 + rw] = *(ulonglong2*)&v;
    }

    const unsigned mb_base = smem_u32(smraw + SM_MBAR);
    if (t == 0) {
#pragma unroll
        for (int m = 0; m < 8; ++m) mbar_init(mb_base + m * 8, 1u);
    }
    __syncthreads();
    if (t == 0) {
#pragma unroll
        for (int src = 0; src < 4; ++src) {
            if (src == r) continue;
            mbar_arm_tx(mb_base + (src * 2 + 0) * 8, 512u);
            mbar_arm_tx(mb_base + (src * 2 + 1) * 8, 512u);
        }
    }

    // h0 into parity-0 buffer (blocked layout)
    {
        const int k = t;
        const int rk = k >> 6, kl = k & 63;
        const int base = rk * 128 + (kl >> 2) * 8 + (kl & 3);
#pragma unroll
        for (int b = 0; b < 2; ++b)
            h_sf[base + b * 4] = h0[(size_t)(cid * 2 + b) * 256 + k];
    }
    __syncthreads();
    asm volatile("barrier.cluster.arrive.aligned;" ::: "memory");
    asm volatile("barrier.cluster.wait.aligned;" ::: "memory");

    const bool cell = (t < 128);
    const int o_c = t >> 1, b_c = t & 1;
    const int o_g = r * 64 + o_c;
    const int b_g = cid * 2 + b_c;
    float creg = cell ? c0[(size_t)b_g * 256 + o_g] : 0.0f;

    float xgv[4];
    if (cell) {
        const float* xp = g_xg + (size_t)(0 * 64 + b_g) * 1024 + o_g;
#pragma unroll
        for (int gg = 0; gg < 4; ++gg) xgv[gg] = __ldcg(xp + gg * 256);
    }

    float* hT = out + (size_t)B_ * S_ * O_;
    float* cT = hT + (size_t)B_ * O_;
    const unsigned hs_base = smem_u32(h_sf);
    unsigned parmask = 0u;

    int p = 0;
    for (int s = 0; s < S_; ++s, p ^= 1) {
        const float* hp = h_sf + p * 512;
        ULL acc0 = 0ULL, acc1 = 0ULL;

        // chunk 0: own block (registers, no wait)
        {
            const float* hb = hp + r * 128;
#pragma unroll
            for (int k4 = 0; k4 < 16; ++k4) {
                const ulonglong2 h0v = *(const ulonglong2*)(hb + k4 * 8);
                const ulonglong2 h1v = *(const ulonglong2*)(hb + k4 * 8 + 4);
                acc0 = ffma2(h0v.x, wpr[0][2 * k4], acc0);
                acc0 = ffma2(h0v.y, wpr[0][2 * k4 + 1], acc0);
                acc1 = ffma2(h1v.x, wpr[0][2 * k4], acc1);
                acc1 = ffma2(h1v.y, wpr[0][2 * k4 + 1], acc1);
            }
        }
        // chunk 1: block (r+1)&3 (registers)
        {
            const int blk = (r + 1) & 3;
            if (s > 0) {
                const int m = blk * 2 + p;
                mbar_wait_cluster(mb_base + m * 8u, (parmask >> m) & 1u);
                parmask ^= (1u << m);
            }
            const float* hb = hp + blk * 128;
#pragma unroll
            for (int k4 = 0; k4 < 16; ++k4) {
                const ulonglong2 h0v = *(const ulonglong2*)(hb + k4 * 8);
                const ulonglong2 h1v = *(const ulonglong2*)(hb + k4 * 8 + 4);
                acc0 = ffma2(h0v.x, wpr[1][2 * k4], acc0);
                acc0 = ffma2(h0v.y, wpr[1][2 * k4 + 1], acc0);
                acc1 = ffma2(h1v.x, wpr[1][2 * k4], acc1);
                acc1 = ffma2(h1v.y, wpr[1][2 * k4 + 1], acc1);
            }
        }
        // chunks 2,3: smem weights
#pragma unroll
        for (int j = 0; j < 2; ++j) {
            const int blk = (r + 2 + j) & 3;
            if (s > 0) {
                const int m = blk * 2 + p;
                mbar_wait_cluster(mb_base + m * 8u, (parmask >> m) & 1u);
                parmask ^= (1u << m);
            }
            const float* hb = hp + blk * 128;
            const ulonglong2* wb = wS + (size_t)(j * 16) * 256 + t;
#pragma unroll
            for (int k4 = 0; k4 < 16; ++k4) {
                const ulonglong2 wv = wb[k4 * 256];
                const ulonglong2 h0v = *(const ulonglong2*)(hb + k4 * 8);
                const ulonglong2 h1v = *(const ulonglong2*)(hb + k4 * 8 + 4);
                acc0 = ffma2(h0v.x, wv.x, acc0);
                acc0 = ffma2(h0v.y, wv.y, acc0);
                acc1 = ffma2(h1v.x, wv.x, acc1);
                acc1 = ffma2(h1v.y, wv.y, acc1);
            }
        }

        if (s > 0 && t < 3) {
            const int src = (r + 1 + t) & 3;
            mbar_arm_tx(mb_base + (unsigned)(src * 2 + p) * 8u, 512u);
        }

        gsm[t]      = f2lo(acc0) + f2hi(acc0);   // batch 0
        gsm[GS + t] = f2lo(acc1) + f2hi(acc1);   // batch 1
        __syncthreads();

        if (cell) {
            const float* gb = gsm + b_c * GS;
            const float gf = gb[o_c]       + xgv[0];
            const float gi = gb[64 + o_c]  + xgv[1];
            const float gc = gb[128 + o_c] + xgv[2];
            const float go = gb[192 + o_c] + xgv[3];
            const float fg  = sigf(gf);
            const float ig  = sigf(gi);
            const float cg  = tanhx(gc);
            const float ogt = sigf(go);
            creg = creg * fg + ig * cg;
            const float hv = ogt * tanhx(creg);
            out[((size_t)b_g * S_ + s) * 256 + o_g] = hv;
            if (s == S_ - 1) {
                hT[(size_t)b_g * 256 + o_g] = hv;
                cT[(size_t)b_g * 256 + o_g] = creg;
            } else {
                const int q = p ^ 1;
                const int boff = (o_c >> 2) * 8 + b_c * 4 + (o_c & 3);
                h_sf[q * 512 + r * 128 + boff] = hv;   // own block (copy src)
                // EARLY COPY: cell-scoped barrier covers all writers of the
                // source block; then issue the same 3x512B copies as R12.
                asm volatile("bar.sync 1, 128;" ::: "memory");
                if (t < 3) {
                    asm volatile("fence.proxy.async.shared::cta;" ::: "memory");
                    const int dr = (r + 1 + t) & 3;
                    const unsigned src = hs_base +
                        (unsigned)(q * 512 + r * 128) * 4u;
                    const unsigned dst = mapa_rank(src, dr);
                    const unsigned mbr = mapa_rank(
                        mb_base + (unsigned)(r * 2 + q) * 8u, dr);
                    dsm_bulk_copy(dst, src, 512u, mbr);
                }
            }
        }
        __syncthreads();

        if (s < S_ - 1 && cell) {
            const float* xp = g_xg + (size_t)((s + 1) * 64 + b_g) * 1024 + o_g;
#pragma unroll
            for (int gg = 0; gg < 4; ++gg) xgv[gg] = __ldcg(xp + gg * 256);
        }
    }

    asm volatile("barrier.cluster.arrive.aligned;" ::: "memory");
    asm volatile("barrier.cluster.wait.aligned;" ::: "memory");
}

// ---------------------------------------------------------------------------
// launch
// ---------------------------------------------------------------------------
extern "C" void kernel_launch(void* const* d_in, const int* in_sizes, int n_in,
                              void* d_out, int out_size) {
    (void)in_sizes; (void)n_in; (void)out_size;
    const float* x  = (const float*)d_in[0];
    const float* h0 = (const float*)d_in[1];
    const float* c0 = (const float*)d_in[2];
    const float* Wh = (const float*)d_in[3];
    const float* bh = (const float*)d_in[4];
    const float* Wx = (const float*)d_in[5];
    const float* bx = (const float*)d_in[6];
    float* out = (float*)d_out;

    cudaFuncSetAttribute(lstm_rec_kernel,
                         cudaFuncAttributeMaxDynamicSharedMemorySize, SM_TOTAL);

    conv_x_kernel<<<32768, 256>>>(x);
    conv_w_kernel<<<1024, 256>>>(Wx, bx, bh);
    gemm_bf16_kernel<<<dim3(8, 256), 256>>>();
    lstm_rec_kernel<<<128, 256, SM_TOTAL>>>(h0, c0, Wh, out);
}

// round 17
// speedup vs baseline: 1.1650x; 1.0844x over previous
#include <cuda_runtime.h>
#include <cuda_bf16.h>
#include <mma.h>

using namespace nvcuda;

#define B_ 64
#define S_ 512
#define I_ 256
#define O_ 256
#define KPA 544   // A': [hi(256) | lo(256) | ones(32)]  (hi reused for segment 2)
#define KPB 800   // B': [Whi(256) | Whi(256) | Wlo(256) | bias(2) pad(30)]

typedef unsigned long long ULL;

// Scratch: xg[m][n], m = s*64 + b (32768), n = gate*256 + o (1024). 134 MB.
__device__ float g_xg[(size_t)S_ * B_ * 4 * O_];
// bf16 split operands
__device__ __nv_bfloat16 g_abf[(size_t)32768 * KPA];   // 35.7 MB
__device__ __nv_bfloat16 g_bbf[(size_t)1024 * KPB];    // 1.6 MB

// ---------------------------------------------------------------------------
// helpers
// ---------------------------------------------------------------------------
__device__ __forceinline__ ULL ffma2(ULL a, ULL b, ULL c) {
    ULL d;
    asm("fma.rn.f32x2 %0, %1, %2, %3;" : "=l"(d) : "l"(a), "l"(b), "l"(c));
    return d;
}
__device__ __forceinline__ float f2lo(ULL v) { return __uint_as_float((unsigned)v); }
__device__ __forceinline__ float f2hi(ULL v) { return __uint_as_float((unsigned)(v >> 32)); }
__device__ __forceinline__ float sigf(float x) { return 1.0f / (1.0f + __expf(-x)); }
__device__ __forceinline__ float tanhx(float x) { return 2.0f * sigf(2.0f * x) - 1.0f; }
__device__ __forceinline__ unsigned smem_u32(const void* p) {
    return (unsigned)__cvta_generic_to_shared(p);
}
__device__ __forceinline__ unsigned mapa_rank(unsigned local_addr, int rank) {
    unsigned ra;
    asm volatile("mapa.shared::cluster.u32 %0, %1, %2;"
                 : "=r"(ra) : "r"(local_addr), "r"(rank));
    return ra;
}
__device__ __forceinline__ void mbar_init(unsigned mbar, unsigned cnt) {
    asm volatile("mbarrier.init.shared.b64 [%0], %1;" :: "r"(mbar), "r"(cnt) : "memory");
}
__device__ __forceinline__ void mbar_arm_tx(unsigned mbar, unsigned tx) {
    asm volatile("mbarrier.arrive.expect_tx.shared.b64 _, [%0], %1;"
                 :: "r"(mbar), "r"(tx) : "memory");
}
__device__ __forceinline__ void mbar_wait_cluster(unsigned mbar, unsigned parity) {
    asm volatile(
        "{\n\t.reg .pred P1;\n\t"
        "WAIT_%=:\n\t"
        "mbarrier.try_wait.parity.acquire.cluster.shared::cta.b64 P1, [%0], %1, 0x989680;\n\t"
        "@P1 bra.uni DONE_%=;\n\t"
        "bra.uni WAIT_%=;\n\t"
        "DONE_%=:\n\t}"
        :: "r"(mbar), "r"(parity) : "memory");
}
__device__ __forceinline__ void dsm_bulk_copy(unsigned dst_cluster, unsigned src_cta,
                                              unsigned bytes, unsigned mbar_cluster) {
    asm volatile(
        "cp.async.bulk.shared::cluster.shared::cta.mbarrier::complete_tx::bytes "
        "[%0], [%1], %2, [%3];"
        :: "r"(dst_cluster), "r"(src_cta), "r"(bytes), "r"(mbar_cluster) : "memory");
}
__device__ __forceinline__ void cp16(unsigned smem_dst, const void* gmem_src) {
    asm volatile("cp.async.cg.shared.global [%0], [%1], 16;"
                 :: "r"(smem_dst), "l"(gmem_src) : "memory");
}

// ---------------------------------------------------------------------------
// Phase 1a: bf16-split conversion.
// ---------------------------------------------------------------------------
__global__ void conv_x_kernel(const float* __restrict__ x) {
    const int m = blockIdx.x;          // 0..32767
    const int t = threadIdx.x;         // 0..255
    const int b = m & 63, s = m >> 6;
    const float f = x[((size_t)b * S_ + s) * I_ + t];
    const __nv_bfloat16 hi = __float2bfloat16(f);
    const __nv_bfloat16 lo = __float2bfloat16(f - __bfloat162float(hi));
    __nv_bfloat16* row = g_abf + (size_t)m * KPA;
    row[t]       = hi;
    row[256 + t] = lo;
    if (t < 32)
        row[512 + t] = __float2bfloat16((t < 2) ? 1.0f : 0.0f);
}

__global__ void conv_w_kernel(const float* __restrict__ Wx,
                              const float* __restrict__ bx,
                              const float* __restrict__ bh) {
    const int n = blockIdx.x;          // 0..1023
    const int t = threadIdx.x;
    const float f = Wx[(size_t)n * I_ + t];
    const __nv_bfloat16 hi = __float2bfloat16(f);
    const __nv_bfloat16 lo = __float2bfloat16(f - __bfloat162float(hi));
    __nv_bfloat16* row = g_bbf + (size_t)n * KPB;
    row[t]       = hi;
    row[256 + t] = hi;
    row[512 + t] = lo;
    if (t < 32) {
        __nv_bfloat16 v = __float2bfloat16(0.0f);
        if (t < 2) {
            const float bias = bx[n] + bh[n];
            const __nv_bfloat16 bhi = __float2bfloat16(bias);
            v = (t == 0) ? bhi : __float2bfloat16(bias - __bfloat162float(bhi));
        }
        row[768 + t] = v;
    }
}

// ---------------------------------------------------------------------------
// Phase 1b: xg = A'(32768x800 logical) @ B'^T via wmma bf16, cp.async 3-stage.
//   BM=BN=128, BK=32, 256 thr, 8 warps (4m x 2n), warp tile 32x64.
//   A global reads remapped: stage ks -> aoff (hi segment reused for seg 2).
// ---------------------------------------------------------------------------
#define BKG 32
#define KSTAGES 25
#define ROWB 40                       // smem row stride in bf16 (80 B)
#define ABUF_B (128 * ROWB * 2)       // 10240 B per buffer
#define GEMM_SMEM (6 * ABUF_B)        // 3 A + 3 B = 61440 B

__device__ __forceinline__ int a_off(int ks) {
    return (ks < 16) ? ks * 32 : (ks < 24) ? (ks - 16) * 32 : 512;
}

__global__ void __launch_bounds__(256, 1) gemm_bf16_kernel() {
    extern __shared__ __align__(16) unsigned char gsm[];
    // As[buf] at buf*ABUF_B; Bs[buf] at 3*ABUF_B + buf*ABUF_B
    const int t  = threadIdx.x;
    const int bn = blockIdx.x;   // 0..7
    const int bm = blockIdx.y;   // 0..255
    const int wid = t >> 5;
    const int wm = wid & 3;
    const int wn = wid >> 2;

    const int row  = t >> 1;     // 0..127
    const int half = t & 1;
    const __nv_bfloat16* agr = g_abf + (size_t)(bm * 128 + row) * KPA + half * 16;
    const __nv_bfloat16* bgr = g_bbf + (size_t)(bn * 128 + row) * KPB + half * 16;
    const unsigned sb = smem_u32(gsm);
    const unsigned a_dst = sb + (unsigned)(row * ROWB + half * 16) * 2u;
    const unsigned b_dst = a_dst + 3u * ABUF_B;

    auto issue = [&](int ks, int buf) {
        const __nv_bfloat16* as = agr + a_off(ks);
        const __nv_bfloat16* bs = bgr + ks * 32;
        const unsigned ad = a_dst + (unsigned)buf * ABUF_B;
        const unsigned bd = b_dst + (unsigned)buf * ABUF_B;
        cp16(ad, as);
        cp16(ad + 16u, as + 8);
        cp16(bd, bs);
        cp16(bd + 16u, bs + 8);
    };

    wmma::fragment<wmma::accumulator, 16, 16, 16, float> cf[2][4];
#pragma unroll
    for (int i = 0; i < 2; ++i)
#pragma unroll
        for (int j = 0; j < 4; ++j) wmma::fill_fragment(cf[i][j], 0.0f);

    issue(0, 0);
    asm volatile("cp.async.commit_group;" ::: "memory");
    issue(1, 1);
    asm volatile("cp.async.commit_group;" ::: "memory");

    for (int ks = 0; ks < KSTAGES; ++ks) {
        asm volatile("cp.async.wait_group 1;" ::: "memory");
        __syncthreads();
        if (ks + 2 < KSTAGES) issue(ks + 2, (ks + 2) % 3);
        asm volatile("cp.async.commit_group;" ::: "memory");

        const int cur = ks % 3;
        const __nv_bfloat16* As =
            (const __nv_bfloat16*)(gsm + (size_t)cur * ABUF_B);
        const __nv_bfloat16* Bs =
            (const __nv_bfloat16*)(gsm + (size_t)(3 + cur) * ABUF_B);
#pragma unroll
        for (int k16 = 0; k16 < 2; ++k16) {
            wmma::fragment<wmma::matrix_a, 16, 16, 16, __nv_bfloat16,
                           wmma::row_major> af[2];
            wmma::fragment<wmma::matrix_b, 16, 16, 16, __nv_bfloat16,
                           wmma::col_major> bfr[4];
#pragma unroll
            for (int i = 0; i < 2; ++i)
                wmma::load_matrix_sync(af[i],
                    As + (wm * 32 + i * 16) * ROWB + k16 * 16, ROWB);
#pragma unroll
            for (int j = 0; j < 4; ++j)
                wmma::load_matrix_sync(bfr[j],
                    Bs + (wn * 64 + j * 16) * ROWB + k16 * 16, ROWB);
#pragma unroll
            for (int i = 0; i < 2; ++i)
#pragma unroll
                for (int j = 0; j < 4; ++j)
                    wmma::mma_sync(cf[i][j], af[i], bfr[j], cf[i][j]);
        }
    }

#pragma unroll
    for (int i = 0; i < 2; ++i) {
        const int m = bm * 128 + wm * 32 + i * 16;
#pragma unroll
        for (int j = 0; j < 4; ++j) {
            const int n = bn * 128 + wn * 64 + j * 16;
            wmma::store_matrix_sync(g_xg + (size_t)m * 1024 + n, cf[i][j],
                                    1024, wmma::mem_row_major);
        }
    }
}

// ---------------------------------------------------------------------------
// Phase 2: EXACT R12 recurrence (protected best). Untouched.
// ---------------------------------------------------------------------------
// dynamic smem (bytes):
//   [0, 131072)        ulonglong2 wS[2][16][256]  ([j][k4][row])
//   [131072, 135168)   float h[2][512]            (parity x 4 blocks x 128 f)
//   [135168, 137248)   float gsm[2][260]
//   [137248, 137312)   ULL mbar[8]                (m = src*2 + parity)
#define SM_WS    0
#define SM_HS    131072
#define SM_GSM   135168
#define SM_MBAR  137248
#define SM_TOTAL 137312
#define GS       260

__global__ void __cluster_dims__(4, 1, 1) __launch_bounds__(256, 1)
lstm_rec_kernel(const float* __restrict__ h0, const float* __restrict__ c0,
                const float* __restrict__ Wh, float* __restrict__ out) {
    extern __shared__ __align__(16) unsigned char smraw[];
    ulonglong2* wS = (ulonglong2*)(smraw + SM_WS);   // [j*16 + k4][row]
    float* h_sf    = (float*)(smraw + SM_HS);        // [p][512]
    float* gsm     = (float*)(smraw + SM_GSM);       // [b][GS]

    const int t   = threadIdx.x;
    const int r   = blockIdx.x & 3;        // cluster rank
    const int cid = blockIdx.x >> 2;       // 0..31

    const int grow = (t >> 6) * 256 + r * 64 + (t & 63);
    const float* wrow = Wh + (size_t)grow * 256;

    // register weights: blocks {r, (r+1)&3}
    ULL wpr[2][32];
#pragma unroll
    for (int j = 0; j < 2; ++j) {
        const int blk = (r + j) & 3;
#pragma unroll
        for (int k2 = 0; k2 < 32; ++k2)
            wpr[j][k2] = *(const ULL*)(wrow + blk * 64 + 2 * k2);
    }

    // smem weights: blocks {(r+2)&3, (r+3)&3}, layout [j][k4][row]
    for (int idx = t; idx < 2 * 16 * 256; idx += 256) {
        const int j = idx >> 12, k4 = (idx >> 8) & 15, rw = idx & 255;
        const int grw = (rw >> 6) * 256 + r * 64 + (rw & 63);
        const int blk = (r + 2 + j) & 3;
        float4 v = *(const float4*)(Wh + (size_t)grw * 256 + blk * 64 + k4 * 4);
        wS[(j * 16 + k4) * 256 + rw] = *(ulonglong2*)&v;
    }

    const unsigned mb_base = smem_u32(smraw + SM_MBAR);
    if (t == 0) {
#pragma unroll
        for (int m = 0; m < 8; ++m) mbar_init(mb_base + m * 8, 1u);
    }
    __syncthreads();
    if (t == 0) {
#pragma unroll
        for (int src = 0; src < 4; ++src) {
            if (src == r) continue;
            mbar_arm_tx(mb_base + (src * 2 + 0) * 8, 512u);
            mbar_arm_tx(mb_base + (src * 2 + 1) * 8, 512u);
        }
    }

    // h0 into parity-0 buffer (blocked layout)
    {
        const int k = t;
        const int rk = k >> 6, kl = k & 63;
        const int base = rk * 128 + (kl >> 2) * 8 + (kl & 3);
#pragma unroll
        for (int b = 0; b < 2; ++b)
            h_sf[base + b * 4] = h0[(size_t)(cid * 2 + b) * 256 + k];
    }
    __syncthreads();
    asm volatile("barrier.cluster.arrive.aligned;" ::: "memory");
    asm volatile("barrier.cluster.wait.aligned;" ::: "memory");

    const bool cell = (t < 128);
    const int o_c = t >> 1, b_c = t & 1;
    const int o_g = r * 64 + o_c;
    const int b_g = cid * 2 + b_c;
    float creg = cell ? c0[(size_t)b_g * 256 + o_g] : 0.0f;

    float xgv[4];
    if (cell) {
        const float* xp = g_xg + (size_t)(0 * 64 + b_g) * 1024 + o_g;
#pragma unroll
        for (int gg = 0; gg < 4; ++gg) xgv[gg] = __ldcg(xp + gg * 256);
    }

    float* hT = out + (size_t)B_ * S_ * O_;
    float* cT = hT + (size_t)B_ * O_;
    const unsigned hs_base = smem_u32(h_sf);
    unsigned parmask = 0u;

    int p = 0;
    for (int s = 0; s < S_; ++s, p ^= 1) {
        const float* hp = h_sf + p * 512;
        ULL acc0 = 0ULL, acc1 = 0ULL;

        // chunk 0: own block (registers, no wait)
        {
            const float* hb = hp + r * 128;
#pragma unroll
            for (int k4 = 0; k4 < 16; ++k4) {
                const ulonglong2 h0v = *(const ulonglong2*)(hb + k4 * 8);
                const ulonglong2 h1v = *(const ulonglong2*)(hb + k4 * 8 + 4);
                acc0 = ffma2(h0v.x, wpr[0][2 * k4], acc0);
                acc0 = ffma2(h0v.y, wpr[0][2 * k4 + 1], acc0);
                acc1 = ffma2(h1v.x, wpr[0][2 * k4], acc1);
                acc1 = ffma2(h1v.y, wpr[0][2 * k4 + 1], acc1);
            }
        }
        // chunk 1: block (r+1)&3 (registers)
        {
            const int blk = (r + 1) & 3;
            if (s > 0) {
                const int m = blk * 2 + p;
                mbar_wait_cluster(mb_base + m * 8u, (parmask >> m) & 1u);
                parmask ^= (1u << m);
            }
            const float* hb = hp + blk * 128;
#pragma unroll
            for (int k4 = 0; k4 < 16; ++k4) {
                const ulonglong2 h0v = *(const ulonglong2*)(hb + k4 * 8);
                const ulonglong2 h1v = *(const ulonglong2*)(hb + k4 * 8 + 4);
                acc0 = ffma2(h0v.x, wpr[1][2 * k4], acc0);
                acc0 = ffma2(h0v.y, wpr[1][2 * k4 + 1], acc0);
                acc1 = ffma2(h1v.x, wpr[1][2 * k4], acc1);
                acc1 = ffma2(h1v.y, wpr[1][2 * k4 + 1], acc1);
            }
        }
        // chunks 2,3: smem weights
#pragma unroll
        for (int j = 0; j < 2; ++j) {
            const int blk = (r + 2 + j) & 3;
            if (s > 0) {
                const int m = blk * 2 + p;
                mbar_wait_cluster(mb_base + m * 8u, (parmask >> m) & 1u);
                parmask ^= (1u << m);
            }
            const float* hb = hp + blk * 128;
            const ulonglong2* wb = wS + (size_t)(j * 16) * 256 + t;
#pragma unroll
            for (int k4 = 0; k4 < 16; ++k4) {
                const ulonglong2 wv = wb[k4 * 256];
                const ulonglong2 h0v = *(const ulonglong2*)(hb + k4 * 8);
                const ulonglong2 h1v = *(const ulonglong2*)(hb + k4 * 8 + 4);
                acc0 = ffma2(h0v.x, wv.x, acc0);
                acc0 = ffma2(h0v.y, wv.y, acc0);
                acc1 = ffma2(h1v.x, wv.x, acc1);
                acc1 = ffma2(h1v.y, wv.y, acc1);
            }
        }

        if (s > 0 && t < 3) {
            const int src = (r + 1 + t) & 3;
            mbar_arm_tx(mb_base + (unsigned)(src * 2 + p) * 8u, 512u);
        }

        gsm[t]      = f2lo(acc0) + f2hi(acc0);   // batch 0
        gsm[GS + t] = f2lo(acc1) + f2hi(acc1);   // batch 1
        __syncthreads();

        if (cell) {
            const float* gb = gsm + b_c * GS;
            const float gf = gb[o_c]       + xgv[0];
            const float gi = gb[64 + o_c]  + xgv[1];
            const float gc = gb[128 + o_c] + xgv[2];
            const float go = gb[192 + o_c] + xgv[3];
            const float fg  = sigf(gf);
            const float ig  = sigf(gi);
            const float cg  = tanhx(gc);
            const float ogt = sigf(go);
            creg = creg * fg + ig * cg;
            const float hv = ogt * tanhx(creg);
            out[((size_t)b_g * S_ + s) * 256 + o_g] = hv;
            if (s == S_ - 1) {
                hT[(size_t)b_g * 256 + o_g] = hv;
                cT[(size_t)b_g * 256 + o_g] = creg;
            } else {
                const int q = p ^ 1;
                const int boff = (o_c >> 2) * 8 + b_c * 4 + (o_c & 3);
                h_sf[q * 512 + r * 128 + boff] = hv;   // own block (copy src)
            }
        }
        __syncthreads();

        if (s < S_ - 1) {
            const int q = p ^ 1;
            if (t < 3) {
                asm volatile("fence.proxy.async.shared::cta;" ::: "memory");
                const int dr = (r + 1 + t) & 3;
                const unsigned src = hs_base + (unsigned)(q * 512 + r * 128) * 4u;
                const unsigned dst = mapa_rank(src, dr);
                const unsigned mbr = mapa_rank(mb_base + (unsigned)(r * 2 + q) * 8u, dr);
                dsm_bulk_copy(dst, src, 512u, mbr);
            }
            if (cell) {
                const float* xp = g_xg + (size_t)((s + 1) * 64 + b_g) * 1024 + o_g;
#pragma unroll
                for (int gg = 0; gg < 4; ++gg) xgv[gg] = __ldcg(xp + gg * 256);
            }
        }
    }

    asm volatile("barrier.cluster.arrive.aligned;" ::: "memory");
    asm volatile("barrier.cluster.wait.aligned;" ::: "memory");
}

// ---------------------------------------------------------------------------
// launch
// ---------------------------------------------------------------------------
extern "C" void kernel_launch(void* const* d_in, const int* in_sizes, int n_in,
                              void* d_out, int out_size) {
    (void)in_sizes; (void)n_in; (void)out_size;
    const float* x  = (const float*)d_in[0];
    const float* h0 = (const float*)d_in[1];
    const float* c0 = (const float*)d_in[2];
    const float* Wh = (const float*)d_in[3];
    const float* bh = (const float*)d_in[4];
    const float* Wx = (const float*)d_in[5];
    const float* bx = (const float*)d_in[6];
    float* out = (float*)d_out;

    cudaFuncSetAttribute(lstm_rec_kernel,
                         cudaFuncAttributeMaxDynamicSharedMemorySize, SM_TOTAL);
    cudaFuncSetAttribute(gemm_bf16_kernel,
                         cudaFuncAttributeMaxDynamicSharedMemorySize, GEMM_SMEM);

    conv_x_kernel<<<32768, 256>>>(x);
    conv_w_kernel<<<1024, 256>>>(Wx, bx, bh);
    gemm_bf16_kernel<<<dim3(8, 256), 256, GEMM_SMEM>>>();
    lstm_rec_kernel<<<128, 256, SM_TOTAL>>>(h0, c0, Wh, out);
}